// round 15
// baseline (speedup 1.0000x reference)
#include <cuda_runtime.h>
#include <cuda_bf16.h>
#include <cuda_fp16.h>
#include <cstdint>

#define TOKENS 4096
#define DDIM 768
#define FDIM 3072
#define NEXP 8
#define MAXMB 40   // worst-case sum of per-expert ceil(cnt/128) is 39

// ---------------- scratch (__device__ globals; no allocs allowed) ----------
__device__ __half g_xh[(size_t)TOKENS * DDIM];      // fp16 copy of x
__device__ __half g_h1[(size_t)TOKENS * FDIM];      // fp16 intermediate
__device__ float g_part0[(size_t)TOKENS * DDIM];    // split-K partials (fp32)
__device__ float g_part1[(size_t)TOKENS * DDIM];
__device__ float g_prob[TOKENS];
__device__ int   g_texp[TOKENS];
__device__ int   g_bucket[NEXP * TOKENS];
__device__ int   g_count[NEXP];
__device__ int   g_mbE[MAXMB];      // M-block -> expert
__device__ int   g_mbR[MAXMB];      // M-block -> row0 within bucket
__device__ int   g_nmb;             // number of valid M-blocks
__device__ __half g_w1t[(size_t)NEXP * FDIM * DDIM];  // [e][f][d] K-major
__device__ __half g_w2t[(size_t)NEXP * DDIM * FDIM];  // [e][d][f] K-major

// ---------------- PTX helpers (baseline ISA only) ---------------------------
__device__ __forceinline__ uint32_t smem_to_u32(const void* p) {
    uint32_t a;
    asm("{ .reg .u64 t; cvta.to.shared.u64 t, %1; cvt.u32.u64 %0, t; }"
        : "=r"(a) : "l"(p));
    return a;
}

#define CP16(dst, src) \
    asm volatile("cp.async.cg.shared.global [%0], [%1], 16;" \
                 :: "r"(dst), "l"(src) : "memory")

#define LDSM4(r, addr) \
    asm volatile("ldmatrix.sync.aligned.m8n8.x4.shared.b16 {%0,%1,%2,%3}, [%4];" \
                 : "=r"((r)[0]), "=r"((r)[1]), "=r"((r)[2]), "=r"((r)[3]) \
                 : "r"(addr))

#define MMA(c, a, b0, b1) \
    asm volatile("mma.sync.aligned.m16n8k16.row.col.f32.f16.f16.f32 " \
                 "{%0,%1,%2,%3}, {%4,%5,%6,%7}, {%8,%9}, {%0,%1,%2,%3};" \
                 : "+f"((c)[0]), "+f"((c)[1]), "+f"((c)[2]), "+f"((c)[3]) \
                 : "r"((a)[0]), "r"((a)[1]), "r"((a)[2]), "r"((a)[3]), \
                   "r"(b0), "r"(b1))

__device__ __forceinline__ uint32_t h2pack(float a, float b) {
    __half2 h = __floats2half2_rn(a, b);
    return *(uint32_t*)&h;
}

// 128B-row swizzle: 16B unit u in 0..7, conflict-free XOR on row&7
__device__ __forceinline__ uint32_t offR(uint32_t row, uint32_t u) {
    return row * 128 + ((u ^ (row & 7u)) * 16);
}

// ---------------- small kernels --------------------------------------------
__global__ void reset_kernel() {
    if (threadIdx.x < NEXP) g_count[threadIdx.x] = 0;
}

// Transpose body: fp32 [R][C] slab (expert e) -> fp16 K-major [C][R] plane.
__device__ __forceinline__ void transpose_body(const float* __restrict__ in,
                                               __half* __restrict__ o16,
                                               int R, int C, int e,
                                               int cx, int cy,
                                               float (*s)[65]) {
    const float* I = in + (size_t)e * R * C;
    const size_t obase = (size_t)e * R * C;
    const int r0 = cy * 64, c0 = cx * 64;
    const int tid = threadIdx.x;
#pragma unroll
    for (int i = 0; i < 16; i++) {
        int idx = tid + i * 256;
        int rr = idx >> 6, cc = idx & 63;
        s[rr][cc] = I[(size_t)(r0 + rr) * C + c0 + cc];
    }
    __syncthreads();
#pragma unroll
    for (int i = 0; i < 8; i++) {
        int idx = tid + i * 256;
        int oc = idx >> 5, rp = idx & 31;
        float v0 = s[rp * 2][oc], v1 = s[rp * 2 + 1][oc];
        size_t o = obase + (size_t)(c0 + oc) * R + r0 + rp * 2;
        ((uint32_t*)o16)[o >> 1] = h2pack(v0, v1);
    }
}

// Fused prep: router + x fp16-convert + both weight transposes, all
// CONCURRENT in one launch. Output globals selected INSIDE device code
// (GB300 ATS host-shadow hazard).
#define RT_BLKS (TOKENS / 8)                        // 512
#define XC_BLKS (TOKENS * DDIM / (256 * 8))         // 1536
#define T1_BLKS ((FDIM / 64) * (DDIM / 64) * NEXP)  // 4608
#define T2_BLKS ((DDIM / 64) * (FDIM / 64) * NEXP)  // 4608
__global__ void prep_kernel(const float* __restrict__ x,
                            const float* __restrict__ wr,
                            const float* __restrict__ w1,
                            const float* __restrict__ w2,
                            float* __restrict__ dout,
                            int has_logits, int has_index) {
    __shared__ float s[64][65];
    const int b = blockIdx.x;
    if (b < RT_BLKS) {
        // ---- router: one warp per token --------------------------------
        int warp = threadIdx.x >> 5, lane = threadIdx.x & 31;
        int t = b * 8 + warp;
        float acc[NEXP];
#pragma unroll
        for (int e = 0; e < NEXP; e++) acc[e] = 0.f;
        const float* xr = x + (size_t)t * DDIM;
        for (int d = lane; d < DDIM; d += 32) {
            float xv = xr[d];
#pragma unroll
            for (int e = 0; e < NEXP; e++) acc[e] += xv * wr[d * NEXP + e];
        }
#pragma unroll
        for (int e = 0; e < NEXP; e++) {
#pragma unroll
            for (int o = 16; o; o >>= 1)
                acc[e] += __shfl_xor_sync(0xffffffffu, acc[e], o);
        }
        if (lane == 0) {
            float mx = acc[0]; int mi = 0;
#pragma unroll
            for (int e = 1; e < NEXP; e++)
                if (acc[e] > mx) { mx = acc[e]; mi = e; }
            float sum = 0.f;
#pragma unroll
            for (int e = 0; e < NEXP; e++) sum += expf(acc[e] - mx);
            g_prob[t] = 1.0f / sum;
            g_texp[t] = mi;
            int slot = atomicAdd(&g_count[mi], 1);
            g_bucket[mi * TOKENS + slot] = t;
            if (has_logits) {
                float* lg = dout + (size_t)TOKENS * DDIM + (size_t)t * NEXP;
#pragma unroll
                for (int e = 0; e < NEXP; e++) lg[e] = acc[e];
            }
            if (has_index)
                dout[(size_t)TOKENS * DDIM + (size_t)TOKENS * NEXP + t] = (float)mi;
        }
    } else if (b < RT_BLKS + XC_BLKS) {
        // ---- x: contiguous fp32 -> fp16 --------------------------------
        size_t i = ((size_t)(b - RT_BLKS) * 256 + threadIdx.x) * 8;
        float4 f0 = *(const float4*)(x + i);
        float4 f1 = *(const float4*)(x + i + 4);
        *(uint4*)(g_xh + i) = make_uint4(h2pack(f0.x, f0.y), h2pack(f0.z, f0.w),
                                         h2pack(f1.x, f1.y), h2pack(f1.z, f1.w));
    } else if (b < RT_BLKS + XC_BLKS + T1_BLKS) {
        // ---- transpose w1 [768][3072] -> g_w1t [3072][768] per expert --
        int idx = b - RT_BLKS - XC_BLKS;
        int cx = idx % (FDIM / 64);
        int cy = (idx / (FDIM / 64)) % (DDIM / 64);
        int e = idx / ((FDIM / 64) * (DDIM / 64));
        transpose_body(w1, g_w1t, DDIM, FDIM, e, cx, cy, s);
    } else {
        // ---- transpose w2 [3072][768] -> g_w2t [768][3072] per expert --
        int idx = b - RT_BLKS - XC_BLKS - T1_BLKS;
        int cx = idx % (DDIM / 64);
        int cy = (idx / (DDIM / 64)) % (FDIM / 64);
        int e = idx / ((DDIM / 64) * (FDIM / 64));
        transpose_body(w2, g_w2t, FDIM, DDIM, e, cx, cy, s);
    }
}

// Compact per-expert counts into a dense M-block work table (runs post-router).
__global__ void finalize_kernel() {
    if (threadIdx.x == 0) {
        int n = 0;
        for (int e = 0; e < NEXP; e++) {
            int nb = (g_count[e] + 127) >> 7;
            for (int b = 0; b < nb; b++) {
                g_mbE[n] = e;
                g_mbR[n] = b << 7;
                n++;
            }
        }
        g_nmb = n;
    }
}

// Split-K reduce: out[t] = (part0[t] + part1[t] + b2[e_t]) * prob[t]
__global__ void reduce_kernel(const float* __restrict__ b2,
                              float* __restrict__ out) {
    int idx = blockIdx.x * 256 + threadIdx.x;        // float2 granularity
    if (idx >= TOKENS * DDIM / 2) return;
    int t = idx / (DDIM / 2);
    int d2 = idx % (DDIM / 2);
    float2 p0 = ((const float2*)g_part0)[idx];
    float2 p1 = ((const float2*)g_part1)[idx];
    float2 bb = *(const float2*)(b2 + (size_t)g_texp[t] * DDIM + d2 * 2);
    float p = g_prob[t];
    ((float2*)out)[idx] = make_float2((p0.x + p1.x + bb.x) * p,
                                      (p0.y + p1.y + bb.y) * p);
}

// ---------------- mma.sync gather-GEMM -------------------------------------
// 128x128 CTA tile, K-chunk 64, 3-stage cp.async ring (96 KB; in-flight
// window = 128 K elems, same as R13, at HALF the barrier count). All loads
// are cp.async from fp16 sources (x pre-converted) — zero sync LDG in loop.
// MODE 0 (GEMM1): h1 = relu(xh @ w1[e] + b1[e]) -> fp16; K=768.
// MODE 1 (GEMM2 split-K): g_part[z] = h1[kslice] @ w2[e][kslice,:]; K=1536.
template<int MODE, int KD, int ND, int KSTRIDE>
__global__ __launch_bounds__(256, 2)
void moe_mma(const float* __restrict__ bias) {
    constexpr int NCH = KD / 64;                  // 64-wide K chunks
    constexpr uint32_t P_SZ = 16384;              // 128 rows * 128 B
    constexpr uint32_t A_PL = 0, B_PL = P_SZ;
    constexpr uint32_t STAGE = 2 * P_SZ;          // 32 KB x 3 stages = 96 KB

    extern __shared__ __align__(16) char sbuf[];
    __shared__ int stok[128];

    const int mb = blockIdx.y;
    if (mb >= g_nmb) return;
    const int e = g_mbE[mb];
    const int row0 = g_mbR[mb];
    const int cnt = g_count[e];
    const int col0 = blockIdx.x * 128;
    const int kbeg = (MODE == 1) ? (int)blockIdx.z * KD : 0;
    const int tid = threadIdx.x;

    for (int i = tid; i < 128; i += 256) {
        int r = row0 + i;
        stok[i] = (r < cnt) ? g_bucket[e * TOKENS + r] : -1;
    }
    __syncthreads();

    const uint32_t sb = smem_to_u32(sbuf);

    // ---- loader: thread -> tile-row tid>>1, 64B k-half tid&1 ---------------
    const int lrow = tid >> 1, half = tid & 1;
    const int tok = stok[lrow];
    const int tokc = tok < 0 ? 0 : tok;

    const __half* aP = (MODE == 0 ? g_xh : g_h1)
        + (size_t)tokc * KSTRIDE + kbeg + half * 32;
    const __half* wp = (MODE == 0 ? g_w1t : g_w2t)
        + ((size_t)e * ND + col0 + lrow) * KSTRIDE + kbeg + half * 32;
    uint32_t du[4];
#pragma unroll
    for (int j = 0; j < 4; j++)
        du[j] = offR((uint32_t)lrow, (uint32_t)(half * 4 + j));

    auto issue = [&](int c) {
        const uint32_t bb = sb + (uint32_t)(c % 3) * STAGE;
        const int kk = c * 64;
#pragma unroll
        for (int j = 0; j < 4; j++)
            CP16(bb + B_PL + du[j], wp + kk + j * 8);
#pragma unroll
        for (int j = 0; j < 4; j++)
            CP16(bb + A_PL + du[j], aP + kk + j * 8);
        asm volatile("cp.async.commit_group;" ::: "memory");
    };

    // ---- compute: 8 warps = 4(M) x 2(N); warp tile 32x64 -------------------
    const int w = tid >> 5, l = tid & 31;
    const int m0 = (w & 3) * 32;
    const int n0w = (w >> 2) * 64;
    float acc[2][8][4];
#pragma unroll
    for (int i = 0; i < 2; i++)
#pragma unroll
        for (int j = 0; j < 8; j++)
#pragma unroll
            for (int q = 0; q < 4; q++) acc[i][j][q] = 0.f;

    auto compute = [&](int c) {
        const uint32_t bb = sb + (uint32_t)(c % 3) * STAGE;
#pragma unroll
        for (int s = 0; s < 4; s++) {            // four k16 substeps of chunk
            uint32_t aH[2][4];
#pragma unroll
            for (int i = 0; i < 2; i++) {
                uint32_t ra = bb + A_PL + offR((uint32_t)(m0 + i * 16 + (l & 15)),
                                               (uint32_t)(2 * s + (l >> 4)));
                LDSM4(aH[i], ra);
            }
#pragma unroll
            for (int jj = 0; jj < 4; jj++) {
                uint32_t rb = bb + B_PL +
                    offR((uint32_t)(n0w + jj * 16 + (l & 7) + ((l >> 4) << 3)),
                         (uint32_t)(2 * s + ((l >> 3) & 1)));
                uint32_t tB[4];
                LDSM4(tB, rb);
#pragma unroll
                for (int i = 0; i < 2; i++) {
                    MMA(acc[i][2 * jj],     aH[i], tB[0], tB[1]);
                    MMA(acc[i][2 * jj + 1], aH[i], tB[2], tB[3]);
                }
            }
        }
    };

    // ---- 3-stage pipeline, prefetch distance 2, one barrier per chunk -----
    issue(0);
    issue(1);
    for (int c = 0; c < NCH; c++) {
        if (c + 1 < NCH) {
            asm volatile("cp.async.wait_group 1;" ::: "memory");
        } else {
            asm volatile("cp.async.wait_group 0;" ::: "memory");
        }
        __syncthreads();
        if (c + 2 < NCH) issue(c + 2);
        compute(c);
    }

    // ---- epilogue ----------------------------------------------------------
    float* pout = (MODE == 1) ? (blockIdx.z == 0 ? g_part0 : g_part1) : nullptr;
#pragma unroll
    for (int i = 0; i < 2; i++) {
#pragma unroll
        for (int h2 = 0; h2 < 2; h2++) {
            int mrow = m0 + i * 16 + (l >> 2) + h2 * 8;
            int t2 = stok[mrow];
            if (t2 < 0) continue;
#pragma unroll
            for (int j = 0; j < 8; j++) {
                int col = col0 + n0w + j * 8 + (l & 3) * 2;
                float v0 = acc[i][j][h2 * 2 + 0];
                float v1 = acc[i][j][h2 * 2 + 1];
                if (MODE == 0) {
                    v0 += bias[(size_t)e * ND + col];
                    v1 += bias[(size_t)e * ND + col + 1];
                    v0 = v0 > 0.f ? v0 : 0.f;
                    v1 = v1 > 0.f ? v1 : 0.f;
                    *(uint32_t*)(g_h1 + (size_t)t2 * FDIM + col) = h2pack(v0, v1);
                } else {
                    *(float2*)(pout + (size_t)t2 * DDIM + col) =
                        make_float2(v0, v1);
                }
            }
        }
    }
}

// ---------------- launch ----------------------------------------------------
extern "C" void kernel_launch(void* const* d_in, const int* in_sizes, int n_in,
                              void* d_out, int out_size) {
    const float* x  = (const float*)d_in[0];   // [4,1024,768]
    const float* wr = (const float*)d_in[1];   // [768,8]
    const float* w1 = (const float*)d_in[2];   // [8,768,3072]
    const float* b1 = (const float*)d_in[3];   // [8,3072]
    const float* w2 = (const float*)d_in[4];   // [8,3072,768]
    const float* b2 = (const float*)d_in[5];   // [8,768]
    float* out = (float*)d_out;

    const int hid = TOKENS * DDIM;
    int has_logits = (out_size >= hid + TOKENS * NEXP) ? 1 : 0;
    int has_index  = (out_size >= hid + TOKENS * NEXP + TOKENS) ? 1 : 0;

    const int SMEM_BYTES = 3 * 32768;   // 96 KB dynamic (3-stage ring)
    cudaFuncSetAttribute(moe_mma<0, DDIM, FDIM, DDIM>,
                         cudaFuncAttributeMaxDynamicSharedMemorySize, SMEM_BYTES);
    cudaFuncSetAttribute(moe_mma<1, FDIM / 2, DDIM, FDIM>,
                         cudaFuncAttributeMaxDynamicSharedMemorySize, SMEM_BYTES);

    reset_kernel<<<1, 32>>>();
    // router + x-convert + both weight transposes fused (concurrent blocks)
    prep_kernel<<<RT_BLKS + XC_BLKS + T1_BLKS + T2_BLKS, 256>>>(
        x, wr, w1, w2, out, has_logits, has_index);
    finalize_kernel<<<1, 32>>>();

    // GEMM1: [cnt x 768] @ w1 -> relu -> g_h1 (fp16)
    moe_mma<0, DDIM, FDIM, DDIM>
        <<<dim3(FDIM / 128, MAXMB), 256, SMEM_BYTES>>>(b1);
    // GEMM2: split-K2 over K-halves of 1536 -> fp32 partials
    moe_mma<1, FDIM / 2, DDIM, FDIM>
        <<<dim3(DDIM / 128, MAXMB, 2), 256, SMEM_BYTES>>>(nullptr);
    // combine partials: out = (p0 + p1 + b2[e_t]) * prob
    reduce_kernel<<<(TOKENS * DDIM / 2 + 255) / 256, 256>>>(b2, out);
}

// round 16
// speedup vs baseline: 1.0379x; 1.0379x over previous
#include <cuda_runtime.h>
#include <cuda_bf16.h>
#include <cuda_fp16.h>
#include <cstdint>

#define TOKENS 4096
#define DDIM 768
#define FDIM 3072
#define NEXP 8
#define MAXMB 40   // worst-case sum of per-expert ceil(cnt/128) is 39

// ---------------- scratch (__device__ globals; no allocs allowed) ----------
__device__ __half g_h1[(size_t)TOKENS * FDIM];      // fp16 intermediate
__device__ float g_part0[(size_t)TOKENS * DDIM];    // split-K4 partials (fp32)
__device__ float g_part1[(size_t)TOKENS * DDIM];
__device__ float g_part2[(size_t)TOKENS * DDIM];
__device__ float g_part3[(size_t)TOKENS * DDIM];
__device__ float g_prob[TOKENS];
__device__ int   g_texp[TOKENS];
__device__ int   g_bucket[NEXP * TOKENS];
__device__ int   g_count[NEXP];
__device__ __half g_w1t[(size_t)NEXP * FDIM * DDIM];  // [e][f][d] K-major
__device__ __half g_w2t[(size_t)NEXP * DDIM * FDIM];  // [e][d][f] K-major

// ---------------- PTX helpers (baseline ISA only) ---------------------------
__device__ __forceinline__ uint32_t smem_to_u32(const void* p) {
    uint32_t a;
    asm("{ .reg .u64 t; cvta.to.shared.u64 t, %1; cvt.u32.u64 %0, t; }"
        : "=r"(a) : "l"(p));
    return a;
}

#define CP16(dst, src) \
    asm volatile("cp.async.cg.shared.global [%0], [%1], 16;" \
                 :: "r"(dst), "l"(src) : "memory")

#define STS128(r0, r1, r2, r3, smem_addr) \
    asm volatile("st.shared.v4.b32 [%0], {%1, %2, %3, %4};" \
                 :: "r"(smem_addr), "r"(r0), "r"(r1), "r"(r2), "r"(r3) : "memory")

#define LDSM4(r, addr) \
    asm volatile("ldmatrix.sync.aligned.m8n8.x4.shared.b16 {%0,%1,%2,%3}, [%4];" \
                 : "=r"((r)[0]), "=r"((r)[1]), "=r"((r)[2]), "=r"((r)[3]) \
                 : "r"(addr))

#define MMA(c, a, b0, b1) \
    asm volatile("mma.sync.aligned.m16n8k16.row.col.f32.f16.f16.f32 " \
                 "{%0,%1,%2,%3}, {%4,%5,%6,%7}, {%8,%9}, {%0,%1,%2,%3};" \
                 : "+f"((c)[0]), "+f"((c)[1]), "+f"((c)[2]), "+f"((c)[3]) \
                 : "r"((a)[0]), "r"((a)[1]), "r"((a)[2]), "r"((a)[3]), \
                   "r"(b0), "r"(b1))

__device__ __forceinline__ uint32_t h2pack(float a, float b) {
    __half2 h = __floats2half2_rn(a, b);
    return *(uint32_t*)&h;
}

// swizzled byte offset: 64B rows, 16B unit u in 0..3, conflict-free XOR
__device__ __forceinline__ uint32_t sw64(uint32_t row, uint32_t u) {
    return row * 64 + ((u ^ (row >> 1)) & 3u) * 16;
}

// ---------------- small kernels --------------------------------------------
__global__ void reset_kernel() {
    if (threadIdx.x < NEXP) g_count[threadIdx.x] = 0;
}

// Transpose body: fp32 [R][C] slab (expert e) -> fp16 K-major [C][R] plane.
__device__ __forceinline__ void transpose_body(const float* __restrict__ in,
                                               __half* __restrict__ o16,
                                               int R, int C, int e,
                                               int cx, int cy,
                                               float (*s)[65]) {
    const float* I = in + (size_t)e * R * C;
    const size_t obase = (size_t)e * R * C;
    const int r0 = cy * 64, c0 = cx * 64;
    const int tid = threadIdx.x;
#pragma unroll
    for (int i = 0; i < 16; i++) {
        int idx = tid + i * 256;
        int rr = idx >> 6, cc = idx & 63;
        s[rr][cc] = I[(size_t)(r0 + rr) * C + c0 + cc];
    }
    __syncthreads();
#pragma unroll
    for (int i = 0; i < 8; i++) {
        int idx = tid + i * 256;
        int oc = idx >> 5, rp = idx & 31;
        float v0 = s[rp * 2][oc], v1 = s[rp * 2 + 1][oc];
        size_t o = obase + (size_t)(c0 + oc) * R + r0 + rp * 2;
        ((uint32_t*)o16)[o >> 1] = h2pack(v0, v1);
    }
}

// Fused prep: router blocks + w1-transpose blocks + w2-transpose blocks run
// CONCURRENTLY in one launch. Output globals selected INSIDE device code
// (GB300 ATS host-shadow hazard).
#define RT_BLKS (TOKENS / 8)                       // 512
#define T1_BLKS ((FDIM / 64) * (DDIM / 64) * NEXP) // 4608
#define T2_BLKS ((DDIM / 64) * (FDIM / 64) * NEXP) // 4608
__global__ void prep_kernel(const float* __restrict__ x,
                            const float* __restrict__ wr,
                            const float* __restrict__ w1,
                            const float* __restrict__ w2,
                            float* __restrict__ dout,
                            int has_logits, int has_index) {
    __shared__ float s[64][65];
    const int b = blockIdx.x;
    if (b < RT_BLKS) {
        // ---- router: one warp per token --------------------------------
        int warp = threadIdx.x >> 5, lane = threadIdx.x & 31;
        int t = b * 8 + warp;
        float acc[NEXP];
#pragma unroll
        for (int e = 0; e < NEXP; e++) acc[e] = 0.f;
        const float* xr = x + (size_t)t * DDIM;
        for (int d = lane; d < DDIM; d += 32) {
            float xv = xr[d];
#pragma unroll
            for (int e = 0; e < NEXP; e++) acc[e] += xv * wr[d * NEXP + e];
        }
#pragma unroll
        for (int e = 0; e < NEXP; e++) {
#pragma unroll
            for (int o = 16; o; o >>= 1)
                acc[e] += __shfl_xor_sync(0xffffffffu, acc[e], o);
        }
        if (lane == 0) {
            float mx = acc[0]; int mi = 0;
#pragma unroll
            for (int e = 1; e < NEXP; e++)
                if (acc[e] > mx) { mx = acc[e]; mi = e; }
            float sum = 0.f;
#pragma unroll
            for (int e = 0; e < NEXP; e++) sum += expf(acc[e] - mx);
            g_prob[t] = 1.0f / sum;
            g_texp[t] = mi;
            int slot = atomicAdd(&g_count[mi], 1);
            g_bucket[mi * TOKENS + slot] = t;
            if (has_logits) {
                float* lg = dout + (size_t)TOKENS * DDIM + (size_t)t * NEXP;
#pragma unroll
                for (int e = 0; e < NEXP; e++) lg[e] = acc[e];
            }
            if (has_index)
                dout[(size_t)TOKENS * DDIM + (size_t)TOKENS * NEXP + t] = (float)mi;
        }
    } else if (b < RT_BLKS + T1_BLKS) {
        // ---- transpose w1 [768][3072] -> g_w1t [3072][768] per expert --
        int idx = b - RT_BLKS;
        int cx = idx % (FDIM / 64);
        int cy = (idx / (FDIM / 64)) % (DDIM / 64);
        int e = idx / ((FDIM / 64) * (DDIM / 64));
        transpose_body(w1, g_w1t, DDIM, FDIM, e, cx, cy, s);
    } else {
        // ---- transpose w2 [3072][768] -> g_w2t [768][3072] per expert --
        int idx = b - RT_BLKS - T1_BLKS;
        int cx = idx % (DDIM / 64);
        int cy = (idx / (DDIM / 64)) % (FDIM / 64);
        int e = idx / ((DDIM / 64) * (FDIM / 64));
        transpose_body(w2, g_w2t, FDIM, DDIM, e, cx, cy, s);
    }
}

// Split-K4 reduce: out[t] = (p0+p1+p2+p3 + b2[e_t]) * prob[t]
__global__ void reduce_kernel(const float* __restrict__ b2,
                              float* __restrict__ out) {
    int idx = blockIdx.x * 256 + threadIdx.x;        // float2 granularity
    if (idx >= TOKENS * DDIM / 2) return;
    int t = idx / (DDIM / 2);
    int d2 = idx % (DDIM / 2);
    float2 p0 = ((const float2*)g_part0)[idx];
    float2 p1 = ((const float2*)g_part1)[idx];
    float2 p2 = ((const float2*)g_part2)[idx];
    float2 p3 = ((const float2*)g_part3)[idx];
    float2 bb = *(const float2*)(b2 + (size_t)g_texp[t] * DDIM + d2 * 2);
    float p = g_prob[t];
    ((float2*)out)[idx] =
        make_float2(((p0.x + p1.x) + (p2.x + p3.x) + bb.x) * p,
                    ((p0.y + p1.y) + (p2.y + p3.y) + bb.y) * p);
}

// ---------------- mma.sync gather-GEMM (R13 core, at the mma.sync ceiling) -
// 128x128 CTA tile, K-chunk 32, K-major B via plain LDSM, 5-stage cp.async
// ring with prefetch distance 4. M-block table folded into the prologue
// (derived from g_count; no finalize kernel).
// MODE 0 (GEMM1): h1 = relu(x @ w1[e] + b1[e]) -> fp16; K=768.
// MODE 1 (GEMM2 split-K4): g_part[z] = h1[kslice] @ w2[e][kslice,:]; K=768.
template<int MODE, int KD, int ND, int KSTRIDE>
__global__ __launch_bounds__(256, 2)
void moe_mma(const float* __restrict__ Asrc,
             const float* __restrict__ bias) {
    constexpr int NCH = KD / 32;                  // 32-wide K chunks (24)
    constexpr uint32_t A_SZ = 8192;               // 128 rows * 64 B
    constexpr uint32_t A_PL = 0, B_PL = A_SZ;
    constexpr uint32_t STAGE = 2 * A_SZ;          // 16 KB x 5 stages = 80 KB

    extern __shared__ __align__(16) char sbuf[];
    __shared__ int stok[128];

    // ---- derive (expert, row0) from g_count: finalize folded in ------------
    int e = 0, row0 = 0;
    {
        const int mb = blockIdx.y;
        int n = 0;
        bool found = false;
#pragma unroll
        for (int ee = 0; ee < NEXP; ee++) {
            int nb = (g_count[ee] + 127) >> 7;
            if (!found && mb < n + nb) { e = ee; row0 = (mb - n) << 7; found = true; }
            n += nb;
        }
        if (!found) return;
    }
    const int cnt = g_count[e];
    const int col0 = blockIdx.x * 128;
    const int kbeg = (MODE == 1) ? (int)blockIdx.z * KD : 0;
    const int tid = threadIdx.x;

    for (int i = tid; i < 128; i += 256) {
        int r = row0 + i;
        stok[i] = (r < cnt) ? g_bucket[e * TOKENS + r] : -1;
    }
    __syncthreads();

    const uint32_t sb = smem_to_u32(sbuf);

    // ---- loader: thread -> tile-row tid>>1, k-half (16 elems) tid&1 --------
    const int lrow = tid >> 1, half = tid & 1;
    const int tok = stok[lrow];
    const int tokc = tok < 0 ? 0 : tok;

    const float* aS = Asrc + (size_t)tokc * KSTRIDE + kbeg + half * 16;      // MODE0
    const __half* aHp = g_h1 + (size_t)tokc * KSTRIDE + kbeg + half * 16;    // MODE1
    const __half* wp =
        (MODE == 0 ? g_w1t : g_w2t)
        + ((size_t)e * ND + col0 + lrow) * KSTRIDE + kbeg + half * 16;
    const uint32_t d0 = sw64((uint32_t)lrow, (uint32_t)(half * 2));
    const uint32_t d1 = sw64((uint32_t)lrow, (uint32_t)(half * 2 + 1));

    auto issue = [&](int c) {
        const uint32_t bb = sb + (uint32_t)(c % 5) * STAGE;
        const int kk = c * 32;
        CP16(bb + B_PL + d0, wp + kk);
        CP16(bb + B_PL + d1, wp + kk + 8);
        if (MODE == 0) {
            float4 v0 = *(const float4*)(aS + kk);
            float4 v1 = *(const float4*)(aS + kk + 4);
            float4 v2 = *(const float4*)(aS + kk + 8);
            float4 v3 = *(const float4*)(aS + kk + 12);
            STS128(h2pack(v0.x, v0.y), h2pack(v0.z, v0.w),
                   h2pack(v1.x, v1.y), h2pack(v1.z, v1.w), bb + A_PL + d0);
            STS128(h2pack(v2.x, v2.y), h2pack(v2.z, v2.w),
                   h2pack(v3.x, v3.y), h2pack(v3.z, v3.w), bb + A_PL + d1);
        } else {
            CP16(bb + A_PL + d0, aHp + kk);
            CP16(bb + A_PL + d1, aHp + kk + 8);
        }
        asm volatile("cp.async.commit_group;" ::: "memory");
    };

    // ---- compute: 8 warps = 4(M) x 2(N); warp tile 32x64 -------------------
    const int w = tid >> 5, l = tid & 31;
    const int m0 = (w & 3) * 32;
    const int n0w = (w >> 2) * 64;
    float acc[2][8][4];
#pragma unroll
    for (int i = 0; i < 2; i++)
#pragma unroll
        for (int j = 0; j < 8; j++)
#pragma unroll
            for (int q = 0; q < 4; q++) acc[i][j][q] = 0.f;

    auto compute = [&](int c) {
        const uint32_t bb = sb + (uint32_t)(c % 5) * STAGE;
#pragma unroll
        for (int s = 0; s < 2; s++) {            // two k16 substeps of chunk
            uint32_t aH[2][4];
#pragma unroll
            for (int i = 0; i < 2; i++) {
                uint32_t ra = bb + sw64((uint32_t)(m0 + i * 16 + (l & 15)),
                                        (uint32_t)(2 * s + (l >> 4)));
                LDSM4(aH[i], ra + A_PL);
            }
#pragma unroll
            for (int jj = 0; jj < 4; jj++) {
                uint32_t rb = bb + sw64((uint32_t)(n0w + jj * 16 + (l & 7) + ((l >> 4) << 3)),
                                        (uint32_t)(2 * s + ((l >> 3) & 1)));
                uint32_t tB[4];
                LDSM4(tB, rb + B_PL);
#pragma unroll
                for (int i = 0; i < 2; i++) {
                    MMA(acc[i][2 * jj],     aH[i], tB[0], tB[1]);
                    MMA(acc[i][2 * jj + 1], aH[i], tB[2], tB[3]);
                }
            }
        }
    };

    // ---- 5-stage pipeline, prefetch distance 4, one barrier per chunk -----
    issue(0); issue(1); issue(2); issue(3);
    for (int c = 0; c < NCH; c++) {
        if (c + 4 <= NCH) {
            asm volatile("cp.async.wait_group 3;" ::: "memory");
        } else if (c + 3 == NCH) {
            asm volatile("cp.async.wait_group 2;" ::: "memory");
        } else if (c + 2 == NCH) {
            asm volatile("cp.async.wait_group 1;" ::: "memory");
        } else {
            asm volatile("cp.async.wait_group 0;" ::: "memory");
        }
        __syncthreads();
        if (c + 4 < NCH) issue(c + 4);
        compute(c);
    }

    // ---- epilogue ----------------------------------------------------------
    float* pout = nullptr;
    if (MODE == 1) {
        pout = (blockIdx.z == 0) ? g_part0 : (blockIdx.z == 1) ? g_part1
             : (blockIdx.z == 2) ? g_part2 : g_part3;
    }
#pragma unroll
    for (int i = 0; i < 2; i++) {
#pragma unroll
        for (int h2 = 0; h2 < 2; h2++) {
            int mrow = m0 + i * 16 + (l >> 2) + h2 * 8;
            int t2 = stok[mrow];
            if (t2 < 0) continue;
#pragma unroll
            for (int j = 0; j < 8; j++) {
                int col = col0 + n0w + j * 8 + (l & 3) * 2;
                float v0 = acc[i][j][h2 * 2 + 0];
                float v1 = acc[i][j][h2 * 2 + 1];
                if (MODE == 0) {
                    v0 += bias[(size_t)e * ND + col];
                    v1 += bias[(size_t)e * ND + col + 1];
                    v0 = v0 > 0.f ? v0 : 0.f;
                    v1 = v1 > 0.f ? v1 : 0.f;
                    *(uint32_t*)(g_h1 + (size_t)t2 * FDIM + col) = h2pack(v0, v1);
                } else {
                    *(float2*)(pout + (size_t)t2 * DDIM + col) =
                        make_float2(v0, v1);
                }
            }
        }
    }
}

// ---------------- launch ----------------------------------------------------
extern "C" void kernel_launch(void* const* d_in, const int* in_sizes, int n_in,
                              void* d_out, int out_size) {
    const float* x  = (const float*)d_in[0];   // [4,1024,768]
    const float* wr = (const float*)d_in[1];   // [768,8]
    const float* w1 = (const float*)d_in[2];   // [8,768,3072]
    const float* b1 = (const float*)d_in[3];   // [8,3072]
    const float* w2 = (const float*)d_in[4];   // [8,3072,768]
    const float* b2 = (const float*)d_in[5];   // [8,768]
    float* out = (float*)d_out;

    const int hid = TOKENS * DDIM;
    int has_logits = (out_size >= hid + TOKENS * NEXP) ? 1 : 0;
    int has_index  = (out_size >= hid + TOKENS * NEXP + TOKENS) ? 1 : 0;

    const int SMEM_BYTES = 5 * 16384;   // 80 KB dynamic (5-stage ring)
    cudaFuncSetAttribute(moe_mma<0, DDIM, FDIM, DDIM>,
                         cudaFuncAttributeMaxDynamicSharedMemorySize, SMEM_BYTES);
    cudaFuncSetAttribute(moe_mma<1, FDIM / 4, DDIM, FDIM>,
                         cudaFuncAttributeMaxDynamicSharedMemorySize, SMEM_BYTES);

    reset_kernel<<<1, 32>>>();
    // router + both weight transposes fused (concurrent blocks)
    prep_kernel<<<RT_BLKS + T1_BLKS + T2_BLKS, 256>>>(
        x, wr, w1, w2, out, has_logits, has_index);

    // GEMM1: [cnt x 768] @ w1 -> relu -> g_h1 (fp16)
    moe_mma<0, DDIM, FDIM, DDIM>
        <<<dim3(FDIM / 128, MAXMB), 256, SMEM_BYTES>>>(x, b1);
    // GEMM2: split-K4 over K-quarters of 768 -> fp32 partials
    moe_mma<1, FDIM / 4, DDIM, FDIM>
        <<<dim3(DDIM / 128, MAXMB, 4), 256, SMEM_BYTES>>>(nullptr, nullptr);
    // combine partials: out = (p0+p1+p2+p3 + b2[e_t]) * prob
    reduce_kernel<<<(TOKENS * DDIM / 2 + 255) / 256, 256>>>(b2, out);
}

// round 17
// speedup vs baseline: 1.0630x; 1.0243x over previous
#include <cuda_runtime.h>
#include <cuda_bf16.h>
#include <cuda_fp16.h>
#include <cstdint>

#define TOKENS 4096
#define DDIM 768
#define FDIM 3072
#define NEXP 8
#define MAXMB 40   // worst-case sum of per-expert ceil(cnt/128) is 39

// ---------------- scratch (__device__ globals; no allocs allowed) ----------
__device__ __half g_xh[(size_t)TOKENS * DDIM];      // fp16 copy of x
__device__ __half g_h1[(size_t)TOKENS * FDIM];      // fp16 intermediate
__device__ float g_part0[(size_t)TOKENS * DDIM];    // split-K4 partials (fp32)
__device__ float g_part1[(size_t)TOKENS * DDIM];
__device__ float g_part2[(size_t)TOKENS * DDIM];
__device__ float g_part3[(size_t)TOKENS * DDIM];
__device__ float g_prob[TOKENS];
__device__ int   g_texp[TOKENS];
__device__ int   g_bucket[NEXP * TOKENS];
__device__ int   g_count[NEXP];
__device__ __half g_w1t[(size_t)NEXP * FDIM * DDIM];  // [e][f][d] K-major
__device__ __half g_w2t[(size_t)NEXP * DDIM * FDIM];  // [e][d][f] K-major

// ---------------- PTX helpers (baseline ISA only) ---------------------------
__device__ __forceinline__ uint32_t smem_to_u32(const void* p) {
    uint32_t a;
    asm("{ .reg .u64 t; cvta.to.shared.u64 t, %1; cvt.u32.u64 %0, t; }"
        : "=r"(a) : "l"(p));
    return a;
}

#define CP16(dst, src) \
    asm volatile("cp.async.cg.shared.global [%0], [%1], 16;" \
                 :: "r"(dst), "l"(src) : "memory")

#define LDSM4(r, addr) \
    asm volatile("ldmatrix.sync.aligned.m8n8.x4.shared.b16 {%0,%1,%2,%3}, [%4];" \
                 : "=r"((r)[0]), "=r"((r)[1]), "=r"((r)[2]), "=r"((r)[3]) \
                 : "r"(addr))

#define MMA(c, a, b0, b1) \
    asm volatile("mma.sync.aligned.m16n8k16.row.col.f32.f16.f16.f32 " \
                 "{%0,%1,%2,%3}, {%4,%5,%6,%7}, {%8,%9}, {%0,%1,%2,%3};" \
                 : "+f"((c)[0]), "+f"((c)[1]), "+f"((c)[2]), "+f"((c)[3]) \
                 : "r"((a)[0]), "r"((a)[1]), "r"((a)[2]), "r"((a)[3]), \
                   "r"(b0), "r"(b1))

__device__ __forceinline__ uint32_t h2pack(float a, float b) {
    __half2 h = __floats2half2_rn(a, b);
    return *(uint32_t*)&h;
}

// swizzled byte offset: 64B rows, 16B unit u in 0..3, conflict-free XOR
__device__ __forceinline__ uint32_t sw64(uint32_t row, uint32_t u) {
    return row * 64 + ((u ^ (row >> 1)) & 3u) * 16;
}

// ---------------- small kernels --------------------------------------------
__global__ void reset_kernel() {
    if (threadIdx.x < NEXP) g_count[threadIdx.x] = 0;
}

// Transpose body: fp32 [R][C] slab (expert e) -> fp16 K-major [C][R] plane.
__device__ __forceinline__ void transpose_body(const float* __restrict__ in,
                                               __half* __restrict__ o16,
                                               int R, int C, int e,
                                               int cx, int cy,
                                               float (*s)[65]) {
    const float* I = in + (size_t)e * R * C;
    const size_t obase = (size_t)e * R * C;
    const int r0 = cy * 64, c0 = cx * 64;
    const int tid = threadIdx.x;
#pragma unroll
    for (int i = 0; i < 16; i++) {
        int idx = tid + i * 256;
        int rr = idx >> 6, cc = idx & 63;
        s[rr][cc] = I[(size_t)(r0 + rr) * C + c0 + cc];
    }
    __syncthreads();
#pragma unroll
    for (int i = 0; i < 8; i++) {
        int idx = tid + i * 256;
        int oc = idx >> 5, rp = idx & 31;
        float v0 = s[rp * 2][oc], v1 = s[rp * 2 + 1][oc];
        size_t o = obase + (size_t)(c0 + oc) * R + r0 + rp * 2;
        ((uint32_t*)o16)[o >> 1] = h2pack(v0, v1);
    }
}

// Fused prep: router + x fp16-convert + both weight transposes, all
// CONCURRENT in one launch. Output globals selected INSIDE device code
// (GB300 ATS host-shadow hazard).
#define RT_BLKS (TOKENS / 8)                        // 512
#define XC_BLKS (TOKENS * DDIM / (256 * 8))         // 1536
#define T1_BLKS ((FDIM / 64) * (DDIM / 64) * NEXP)  // 4608
#define T2_BLKS ((DDIM / 64) * (FDIM / 64) * NEXP)  // 4608
__global__ void prep_kernel(const float* __restrict__ x,
                            const float* __restrict__ wr,
                            const float* __restrict__ w1,
                            const float* __restrict__ w2,
                            float* __restrict__ dout,
                            int has_logits, int has_index) {
    __shared__ float s[64][65];
    const int b = blockIdx.x;
    if (b < RT_BLKS) {
        // ---- router: one warp per token --------------------------------
        int warp = threadIdx.x >> 5, lane = threadIdx.x & 31;
        int t = b * 8 + warp;
        float acc[NEXP];
#pragma unroll
        for (int e = 0; e < NEXP; e++) acc[e] = 0.f;
        const float* xr = x + (size_t)t * DDIM;
        for (int d = lane; d < DDIM; d += 32) {
            float xv = xr[d];
#pragma unroll
            for (int e = 0; e < NEXP; e++) acc[e] += xv * wr[d * NEXP + e];
        }
#pragma unroll
        for (int e = 0; e < NEXP; e++) {
#pragma unroll
            for (int o = 16; o; o >>= 1)
                acc[e] += __shfl_xor_sync(0xffffffffu, acc[e], o);
        }
        if (lane == 0) {
            float mx = acc[0]; int mi = 0;
#pragma unroll
            for (int e = 1; e < NEXP; e++)
                if (acc[e] > mx) { mx = acc[e]; mi = e; }
            float sum = 0.f;
#pragma unroll
            for (int e = 0; e < NEXP; e++) sum += expf(acc[e] - mx);
            g_prob[t] = 1.0f / sum;
            g_texp[t] = mi;
            int slot = atomicAdd(&g_count[mi], 1);
            g_bucket[mi * TOKENS + slot] = t;
            if (has_logits) {
                float* lg = dout + (size_t)TOKENS * DDIM + (size_t)t * NEXP;
#pragma unroll
                for (int e = 0; e < NEXP; e++) lg[e] = acc[e];
            }
            if (has_index)
                dout[(size_t)TOKENS * DDIM + (size_t)TOKENS * NEXP + t] = (float)mi;
        }
    } else if (b < RT_BLKS + XC_BLKS) {
        // ---- x: contiguous fp32 -> fp16 --------------------------------
        size_t i = ((size_t)(b - RT_BLKS) * 256 + threadIdx.x) * 8;
        float4 f0 = *(const float4*)(x + i);
        float4 f1 = *(const float4*)(x + i + 4);
        *(uint4*)(g_xh + i) = make_uint4(h2pack(f0.x, f0.y), h2pack(f0.z, f0.w),
                                         h2pack(f1.x, f1.y), h2pack(f1.z, f1.w));
    } else if (b < RT_BLKS + XC_BLKS + T1_BLKS) {
        // ---- transpose w1 [768][3072] -> g_w1t [3072][768] per expert --
        int idx = b - RT_BLKS - XC_BLKS;
        int cx = idx % (FDIM / 64);
        int cy = (idx / (FDIM / 64)) % (DDIM / 64);
        int e = idx / ((FDIM / 64) * (DDIM / 64));
        transpose_body(w1, g_w1t, DDIM, FDIM, e, cx, cy, s);
    } else {
        // ---- transpose w2 [3072][768] -> g_w2t [768][3072] per expert --
        int idx = b - RT_BLKS - XC_BLKS - T1_BLKS;
        int cx = idx % (DDIM / 64);
        int cy = (idx / (DDIM / 64)) % (FDIM / 64);
        int e = idx / ((DDIM / 64) * (FDIM / 64));
        transpose_body(w2, g_w2t, FDIM, DDIM, e, cx, cy, s);
    }
}

// Split-K4 reduce: out[t] = (p0+p1+p2+p3 + b2[e_t]) * prob[t]
__global__ void reduce_kernel(const float* __restrict__ b2,
                              float* __restrict__ out) {
    int idx = blockIdx.x * 256 + threadIdx.x;        // float2 granularity
    if (idx >= TOKENS * DDIM / 2) return;
    int t = idx / (DDIM / 2);
    int d2 = idx % (DDIM / 2);
    float2 p0 = ((const float2*)g_part0)[idx];
    float2 p1 = ((const float2*)g_part1)[idx];
    float2 p2 = ((const float2*)g_part2)[idx];
    float2 p3 = ((const float2*)g_part3)[idx];
    float2 bb = *(const float2*)(b2 + (size_t)g_texp[t] * DDIM + d2 * 2);
    float p = g_prob[t];
    ((float2*)out)[idx] =
        make_float2(((p0.x + p1.x) + (p2.x + p3.x) + bb.x) * p,
                    ((p0.y + p1.y) + (p2.y + p3.y) + bb.y) * p);
}

// ---------------- mma.sync gather-GEMM (R15 core; pure-async A loaders) ----
// 128x128 CTA tile, K-chunk 32, K-major B via plain LDSM, 5-stage cp.async
// ring, prefetch distance 4. ALL mainloop loads are cp.async from fp16
// sources (x pre-converted in prep). M-block table derived in prologue.
// MODE 0 (GEMM1): h1 = relu(xh @ w1[e] + b1[e]) -> fp16; K=768.
// MODE 1 (GEMM2 split-K4): g_part[z] = h1[kslice] @ w2[e][kslice,:]; K=768.
template<int MODE, int KD, int ND, int KSTRIDE>
__global__ __launch_bounds__(256, 2)
void moe_mma(const float* __restrict__ bias) {
    constexpr int NCH = KD / 32;                  // 32-wide K chunks (24)
    constexpr uint32_t A_SZ = 8192;               // 128 rows * 64 B
    constexpr uint32_t A_PL = 0, B_PL = A_SZ;
    constexpr uint32_t STAGE = 2 * A_SZ;          // 16 KB x 5 stages = 80 KB

    extern __shared__ __align__(16) char sbuf[];
    __shared__ int stok[128];

    // ---- derive (expert, row0) from g_count: finalize folded in ------------
    int e = 0, row0 = 0;
    {
        const int mb = blockIdx.y;
        int n = 0;
        bool found = false;
#pragma unroll
        for (int ee = 0; ee < NEXP; ee++) {
            int nb = (g_count[ee] + 127) >> 7;
            if (!found && mb < n + nb) { e = ee; row0 = (mb - n) << 7; found = true; }
            n += nb;
        }
        if (!found) return;
    }
    const int cnt = g_count[e];
    const int col0 = blockIdx.x * 128;
    const int kbeg = (MODE == 1) ? (int)blockIdx.z * KD : 0;
    const int tid = threadIdx.x;

    for (int i = tid; i < 128; i += 256) {
        int r = row0 + i;
        stok[i] = (r < cnt) ? g_bucket[e * TOKENS + r] : -1;
    }
    __syncthreads();

    const uint32_t sb = smem_to_u32(sbuf);

    // ---- loader: thread -> tile-row tid>>1, k-half (16 elems) tid&1 --------
    const int lrow = tid >> 1, half = tid & 1;
    const int tok = stok[lrow];
    const int tokc = tok < 0 ? 0 : tok;

    const __half* aHp = (MODE == 0 ? g_xh : g_h1)
        + (size_t)tokc * KSTRIDE + kbeg + half * 16;
    const __half* wp = (MODE == 0 ? g_w1t : g_w2t)
        + ((size_t)e * ND + col0 + lrow) * KSTRIDE + kbeg + half * 16;
    const uint32_t d0 = sw64((uint32_t)lrow, (uint32_t)(half * 2));
    const uint32_t d1 = sw64((uint32_t)lrow, (uint32_t)(half * 2 + 1));

    auto issue = [&](int c) {
        const uint32_t bb = sb + (uint32_t)(c % 5) * STAGE;
        const int kk = c * 32;
        CP16(bb + B_PL + d0, wp + kk);
        CP16(bb + B_PL + d1, wp + kk + 8);
        CP16(bb + A_PL + d0, aHp + kk);
        CP16(bb + A_PL + d1, aHp + kk + 8);
        asm volatile("cp.async.commit_group;" ::: "memory");
    };

    // ---- compute: 8 warps = 4(M) x 2(N); warp tile 32x64 -------------------
    const int w = tid >> 5, l = tid & 31;
    const int m0 = (w & 3) * 32;
    const int n0w = (w >> 2) * 64;
    float acc[2][8][4];
#pragma unroll
    for (int i = 0; i < 2; i++)
#pragma unroll
        for (int j = 0; j < 8; j++)
#pragma unroll
            for (int q = 0; q < 4; q++) acc[i][j][q] = 0.f;

    auto compute = [&](int c) {
        const uint32_t bb = sb + (uint32_t)(c % 5) * STAGE;
#pragma unroll
        for (int s = 0; s < 2; s++) {            // two k16 substeps of chunk
            uint32_t aH[2][4];
#pragma unroll
            for (int i = 0; i < 2; i++) {
                uint32_t ra = bb + sw64((uint32_t)(m0 + i * 16 + (l & 15)),
                                        (uint32_t)(2 * s + (l >> 4)));
                LDSM4(aH[i], ra + A_PL);
            }
#pragma unroll
            for (int jj = 0; jj < 4; jj++) {
                uint32_t rb = bb + sw64((uint32_t)(n0w + jj * 16 + (l & 7) + ((l >> 4) << 3)),
                                        (uint32_t)(2 * s + ((l >> 3) & 1)));
                uint32_t tB[4];
                LDSM4(tB, rb + B_PL);
#pragma unroll
                for (int i = 0; i < 2; i++) {
                    MMA(acc[i][2 * jj],     aH[i], tB[0], tB[1]);
                    MMA(acc[i][2 * jj + 1], aH[i], tB[2], tB[3]);
                }
            }
        }
    };

    // ---- 5-stage pipeline, prefetch distance 4, one barrier per chunk -----
    issue(0); issue(1); issue(2); issue(3);
    for (int c = 0; c < NCH; c++) {
        if (c + 4 <= NCH) {
            asm volatile("cp.async.wait_group 3;" ::: "memory");
        } else if (c + 3 == NCH) {
            asm volatile("cp.async.wait_group 2;" ::: "memory");
        } else if (c + 2 == NCH) {
            asm volatile("cp.async.wait_group 1;" ::: "memory");
        } else {
            asm volatile("cp.async.wait_group 0;" ::: "memory");
        }
        __syncthreads();
        if (c + 4 < NCH) issue(c + 4);
        compute(c);
    }

    // ---- epilogue ----------------------------------------------------------
    float* pout = nullptr;
    if (MODE == 1) {
        pout = (blockIdx.z == 0) ? g_part0 : (blockIdx.z == 1) ? g_part1
             : (blockIdx.z == 2) ? g_part2 : g_part3;
    }
#pragma unroll
    for (int i = 0; i < 2; i++) {
#pragma unroll
        for (int h2 = 0; h2 < 2; h2++) {
            int mrow = m0 + i * 16 + (l >> 2) + h2 * 8;
            int t2 = stok[mrow];
            if (t2 < 0) continue;
#pragma unroll
            for (int j = 0; j < 8; j++) {
                int col = col0 + n0w + j * 8 + (l & 3) * 2;
                float v0 = acc[i][j][h2 * 2 + 0];
                float v1 = acc[i][j][h2 * 2 + 1];
                if (MODE == 0) {
                    v0 += bias[(size_t)e * ND + col];
                    v1 += bias[(size_t)e * ND + col + 1];
                    v0 = v0 > 0.f ? v0 : 0.f;
                    v1 = v1 > 0.f ? v1 : 0.f;
                    *(uint32_t*)(g_h1 + (size_t)t2 * FDIM + col) = h2pack(v0, v1);
                } else {
                    *(float2*)(pout + (size_t)t2 * DDIM + col) =
                        make_float2(v0, v1);
                }
            }
        }
    }
}

// ---------------- launch ----------------------------------------------------
extern "C" void kernel_launch(void* const* d_in, const int* in_sizes, int n_in,
                              void* d_out, int out_size) {
    const float* x  = (const float*)d_in[0];   // [4,1024,768]
    const float* wr = (const float*)d_in[1];   // [768,8]
    const float* w1 = (const float*)d_in[2];   // [8,768,3072]
    const float* b1 = (const float*)d_in[3];   // [8,3072]
    const float* w2 = (const float*)d_in[4];   // [8,3072,768]
    const float* b2 = (const float*)d_in[5];   // [8,768]
    float* out = (float*)d_out;

    const int hid = TOKENS * DDIM;
    int has_logits = (out_size >= hid + TOKENS * NEXP) ? 1 : 0;
    int has_index  = (out_size >= hid + TOKENS * NEXP + TOKENS) ? 1 : 0;

    const int SMEM_BYTES = 5 * 16384;   // 80 KB dynamic (5-stage ring)
    cudaFuncSetAttribute(moe_mma<0, DDIM, FDIM, DDIM>,
                         cudaFuncAttributeMaxDynamicSharedMemorySize, SMEM_BYTES);
    cudaFuncSetAttribute(moe_mma<1, FDIM / 4, DDIM, FDIM>,
                         cudaFuncAttributeMaxDynamicSharedMemorySize, SMEM_BYTES);

    reset_kernel<<<1, 32>>>();
    // router + x-convert + both weight transposes fused (concurrent blocks)
    prep_kernel<<<RT_BLKS + XC_BLKS + T1_BLKS + T2_BLKS, 256>>>(
        x, wr, w1, w2, out, has_logits, has_index);

    // GEMM1: [cnt x 768] @ w1 -> relu -> g_h1 (fp16)
    moe_mma<0, DDIM, FDIM, DDIM>
        <<<dim3(FDIM / 128, MAXMB), 256, SMEM_BYTES>>>(b1);
    // GEMM2: split-K4 over K-quarters of 768 -> fp32 partials
    moe_mma<1, FDIM / 4, DDIM, FDIM>
        <<<dim3(DDIM / 128, MAXMB, 4), 256, SMEM_BYTES>>>(nullptr);
    // combine partials: out = (p0+p1+p2+p3 + b2[e_t]) * prob
    reduce_kernel<<<(TOKENS * DDIM / 2 + 255) / 256, 256>>>(b2, out);
}